// round 2
// baseline (speedup 1.0000x reference)
#include <cuda_runtime.h>

#define NB 4
#define NC 64
#define NN 8192
#define NK 16
#define NO 64

// Scratch: y1 = inv*(W1-W2) @ x  (gathered with edge_index[1])
//          y2 = inv*W2 @ x + shift (gathered with edge_index[0])
// Layout [B][N][64] so each gather is one contiguous 256B column.
__device__ __align__(16) float g_y1[(size_t)NB * NN * NO];
__device__ __align__(16) float g_y2[(size_t)NB * NN * NO];

typedef unsigned long long u64;

__device__ __forceinline__ u64 pk2(float a, float b) {
    u64 r;
    asm("mov.b64 %0, {%1, %2};" : "=l"(r) : "f"(a), "f"(b));
    return r;
}
__device__ __forceinline__ void fma2(u64& d, u64 a, u64 b) {
    asm("fma.rn.f32x2 %0, %1, %2, %0;" : "+l"(d) : "l"(a), "l"(b));
}
__device__ __forceinline__ void add2(u64& d, u64 a) {
    asm("add.rn.f32x2 %0, %0, %1;" : "+l"(d) : "l"(a));
}

// ---------------------------------------------------------------------------
// Kernel A: per-node dual GEMM, BN folded into weights.
// 128 threads/block, one node per thread, 64 packed-f32x2 accumulators
// (32 output-pairs x 2 matrices). W broadcast from smem (uniform LDS).
// ---------------------------------------------------------------------------
__global__ __launch_bounds__(128) void kA(
    const float* __restrict__ x, const float* __restrict__ W,
    const float* __restrict__ gamma, const float* __restrict__ beta,
    const float* __restrict__ rmean, const float* __restrict__ rvar)
{
    __shared__ u64 sWd[64 * 32];   // (W1-W2)*inv, packed o-pairs, [c][j]
    __shared__ u64 sW2[64 * 32];   // W2*inv, packed o-pairs, [c][j]
    __shared__ u64 sshift[32];     // (beta - mean*inv), packed o-pairs

    const int tid = threadIdx.x;
    const int b   = blockIdx.y;
    const int n   = blockIdx.x * 128 + tid;

    for (int idx = tid; idx < 2048; idx += 128) {
        int c = idx >> 5, j = idx & 31;
        int o0 = 2 * j, o1 = 2 * j + 1;
        float i0 = gamma[o0] * rsqrtf(rvar[o0] + 1e-5f);
        float i1 = gamma[o1] * rsqrtf(rvar[o1] + 1e-5f);
        float a0 = W[o0 * 128 + c], b0 = W[o0 * 128 + 64 + c];
        float a1 = W[o1 * 128 + c], b1 = W[o1 * 128 + 64 + c];
        sWd[idx] = pk2((a0 - b0) * i0, (a1 - b1) * i1);
        sW2[idx] = pk2(b0 * i0, b1 * i1);
    }
    if (tid < 32) {
        int o0 = 2 * tid, o1 = 2 * tid + 1;
        float i0 = gamma[o0] * rsqrtf(rvar[o0] + 1e-5f);
        float i1 = gamma[o1] * rsqrtf(rvar[o1] + 1e-5f);
        sshift[tid] = pk2(beta[o0] - rmean[o0] * i0, beta[o1] - rmean[o1] * i1);
    }
    __syncthreads();

    u64 acc1[32], acc2[32];
#pragma unroll
    for (int j = 0; j < 32; j++) { acc1[j] = 0ULL; acc2[j] = 0ULL; }

    const float* xp = x + (size_t)b * NC * NN + n;
#pragma unroll 4
    for (int c = 0; c < 64; c++) {
        float xv = __ldg(xp + (size_t)c * NN);   // coalesced across warp
        u64 px = pk2(xv, xv);
        const u64* wd = &sWd[c * 32];
        const u64* w2 = &sW2[c * 32];
#pragma unroll
        for (int j = 0; j < 32; j++) {
            fma2(acc1[j], wd[j], px);
            fma2(acc2[j], w2[j], px);
        }
    }

    u64* y1p = (u64*)(g_y1 + (((size_t)b * NN + n) << 6));
    u64* y2p = (u64*)(g_y2 + (((size_t)b * NN + n) << 6));
#pragma unroll
    for (int j = 0; j < 32; j++) {
        y1p[j] = acc1[j];
        add2(acc2[j], sshift[j]);
        y2p[j] = acc2[j];
    }
}

// ---------------------------------------------------------------------------
// Kernel B: per-node edge gather + leaky + max.
// 8 warps/block, each warp handles 4 nodes; lane owns channels (2l, 2l+1).
// Gathers are contiguous float2 -> 256B/warp coalesced L2 reads.
// Output transposed through smem so each warp stores a full 128B line.
// edge_index is int32 in memory (JAX x64 disabled downcasts int64 -> int32).
// ---------------------------------------------------------------------------
__global__ __launch_bounds__(256) void kB(
    const int* __restrict__ ei, float* __restrict__ out)
{
    __shared__ float sm[64 * 33];

    const int tid  = threadIdx.x;
    const int w    = tid >> 5;
    const int lane = tid & 31;
    const int b    = blockIdx.y;
    const int n0   = blockIdx.x * 32;

    const int* e0 = ei + (size_t)b * NN * NK;                    // edge_index[0][b]
    const int* e1 = e0 + (size_t)NB * NN * NK;                   // edge_index[1][b]
    const float NEG_INF = __int_as_float(0xff800000u);

    for (int j = 0; j < 4; j++) {
        const int nl = w * 4 + j;
        const int n  = n0 + nl;
        const size_t base = (size_t)n * NK;

        // lanes 0-15: i0[k], lanes 16-31: i1[k]
        int v;
        if (lane < 16) v = __ldg(e0 + base + lane);
        else           v = __ldg(e1 + base + (lane - 16));

        float m0 = NEG_INF, m1 = NEG_INF;
#pragma unroll
        for (int k = 0; k < 16; k++) {
            int i0 = __shfl_sync(0xffffffffu, v, k);
            int i1 = __shfl_sync(0xffffffffu, v, k + 16);
            const float2 a  = *(const float2*)(g_y1 + (((size_t)b * NN + i1) << 6) + (lane << 1));
            const float2 c2 = *(const float2*)(g_y2 + (((size_t)b * NN + i0) << 6) + (lane << 1));
            float h0 = a.x + c2.x;
            float h1 = a.y + c2.y;
            h0 = fmaxf(h0, 0.2f * h0);      // LeakyReLU(0.2) == max(h, 0.2h)
            h1 = fmaxf(h1, 0.2f * h1);
            m0 = fmaxf(m0, h0);
            m1 = fmaxf(m1, h1);
        }
        sm[(2 * lane)     * 33 + nl] = m0;
        sm[(2 * lane + 1) * 33 + nl] = m1;
    }
    __syncthreads();

#pragma unroll
    for (int i = 0; i < 8; i++) {
        int o = i * 8 + w;
        out[((size_t)(b * NO + o)) * NN + n0 + lane] = sm[o * 33 + lane];
    }
}

extern "C" void kernel_launch(void* const* d_in, const int* in_sizes, int n_in,
                              void* d_out, int out_size)
{
    const float* x     = (const float*)d_in[0];
    const int*   ei    = (const int*)d_in[1];
    const float* W     = (const float*)d_in[2];
    const float* gamma = (const float*)d_in[3];
    const float* beta  = (const float*)d_in[4];
    const float* rmean = (const float*)d_in[5];
    const float* rvar  = (const float*)d_in[6];
    float*       out   = (float*)d_out;

    kA<<<dim3(NN / 128, NB), 128>>>(x, W, gamma, beta, rmean, rvar);
    kB<<<dim3(NN / 32, NB), 256>>>(ei, out);
}

// round 4
// speedup vs baseline: 1.1628x; 1.1628x over previous
#include <cuda_runtime.h>
#include <cuda_fp16.h>

#define NB 4
#define NC 64
#define NN 8192
#define NK 16
#define NO 64
#define EPSV 1e-5f

// Combined y, fp16: [b][n][128] halves. ch 0-63  = y1 = inv*(W1-W2)@x  (gather via e1)
//                                      ch 64-127 = y2 = inv*W2@x + shift (gather via e0)
// One node row = 256B; each gather reads a 128B half-row.
__device__ __align__(16) __half g_y[(size_t)NB * NN * 128];

typedef unsigned long long u64;

__device__ __forceinline__ u64 pk2(float a, float b) {
    u64 r; asm("mov.b64 %0, {%1, %2};" : "=l"(r) : "f"(a), "f"(b)); return r;
}
__device__ __forceinline__ void upk2(u64 v, float& a, float& b) {
    asm("mov.b64 {%0, %1}, %2;" : "=f"(a), "=f"(b) : "l"(v));
}
__device__ __forceinline__ void fma2(u64& d, u64 a, u64 b) {
    asm("fma.rn.f32x2 %0, %1, %2, %0;" : "+l"(d) : "l"(a), "l"(b));
}

// ---------------------------------------------------------------------------
// Kernel A: C[128 outs][128 nodes] tile per block, SGEMM-style.
// 256 threads, thread = 8 outs x 8 nodes, f32x2 accumulators packed over
// output pairs. W staged in two 32-channel chunks (16KB) + X tile (32KB)
// = 48KB static smem -> 2 blocks/SM, grid 256 fits in one wave.
// BN folded: shift pre-loaded into accumulators.
// ---------------------------------------------------------------------------
__global__ __launch_bounds__(256, 2) void kA(
    const float* __restrict__ x, const float* __restrict__ W,
    const float* __restrict__ gamma, const float* __restrict__ beta,
    const float* __restrict__ rmean, const float* __restrict__ rvar)
{
    __shared__ float sW[32 * 128];   // [c-in-chunk][out]
    __shared__ float sX[64 * 128];   // [c][node]

    const int tid = threadIdx.x;
    const int b   = blockIdx.y;
    const int n0  = blockIdx.x * 128;
    const int og  = tid >> 4;        // 16 groups: outs [og*8, og*8+8)
    const int ng  = tid & 15;        // 16 groups: nodes [ng*8, ng*8+8)

    // Load X tile (64 c x 128 nodes), vectorized+coalesced.
    {
        const float4* xp = (const float4*)(x + (size_t)b * NC * NN + n0);
        for (int i = tid; i < 64 * 32; i += 256) {
            int c = i >> 5, j = i & 31;
            ((float4*)sX)[c * 32 + j] = xp[(size_t)c * (NN / 4) + j];
        }
    }

    // Init accumulators with BN shift (only y2 half, outs 64..127).
    u64 acc[4][8];
    {
        u64 sh[4];
#pragma unroll
        for (int j = 0; j < 4; j++) sh[j] = 0ULL;
        if (og >= 8) {
#pragma unroll
            for (int j = 0; j < 4; j++) {
                int o0 = og * 8 + 2 * j - 64;
                int o1 = o0 + 1;
                float i0 = gamma[o0] * rsqrtf(rvar[o0] + EPSV);
                float i1 = gamma[o1] * rsqrtf(rvar[o1] + EPSV);
                sh[j] = pk2(beta[o0] - rmean[o0] * i0, beta[o1] - rmean[o1] * i1);
            }
        }
#pragma unroll
        for (int j = 0; j < 4; j++)
#pragma unroll
            for (int i = 0; i < 8; i++) acc[j][i] = sh[j];
    }

    for (int cc = 0; cc < 2; cc++) {
        __syncthreads();
        // Stage W chunk: channels [cc*32, cc*32+32), BN inv folded.
        for (int i = tid; i < 32 * 128; i += 256) {
            int cl = i >> 7, o = i & 127;
            int c = cc * 32 + cl;
            float v;
            if (o < 64) {
                float inv = gamma[o] * rsqrtf(rvar[o] + EPSV);
                v = (W[o * 128 + c] - W[o * 128 + 64 + c]) * inv;   // (W1-W2)*inv
            } else {
                int o2 = o - 64;
                float inv = gamma[o2] * rsqrtf(rvar[o2] + EPSV);
                v = W[o2 * 128 + 64 + c] * inv;                     // W2*inv
            }
            sW[i] = v;
        }
        __syncthreads();

#pragma unroll 4
        for (int cl = 0; cl < 32; cl++) {
            const float4* wrow = (const float4*)(sW + cl * 128 + og * 8);
            float4 w0 = wrow[0], w1 = wrow[1];
            u64 wp[4] = { pk2(w0.x, w0.y), pk2(w0.z, w0.w),
                          pk2(w1.x, w1.y), pk2(w1.z, w1.w) };
            const float4* xrow = (const float4*)(sX + (cc * 32 + cl) * 128 + ng * 8);
            float4 x0 = xrow[0], x1 = xrow[1];
            float xv[8] = {x0.x, x0.y, x0.z, x0.w, x1.x, x1.y, x1.z, x1.w};
#pragma unroll
            for (int i = 0; i < 8; i++) {
                u64 xs = pk2(xv[i], xv[i]);
#pragma unroll
                for (int j = 0; j < 4; j++) fma2(acc[j][i], wp[j], xs);
            }
        }
    }

    // Epilogue: convert to fp16 pairs, 16B store per node row.
#pragma unroll
    for (int i = 0; i < 8; i++) {
        int n = n0 + ng * 8 + i;
        __half2 h[4];
#pragma unroll
        for (int j = 0; j < 4; j++) {
            float a, bq; upk2(acc[j][i], a, bq);
            h[j] = __floats2half2_rn(a, bq);
        }
        *(uint4*)(&g_y[(((size_t)b * NN + n) << 7) + og * 8]) = *(uint4*)h;
    }
}

// ---------------------------------------------------------------------------
// Kernel B: per-node edge gather + leaky + max, fp16 y (halved L2 bytes).
// 8 warps/block, warp handles 4 nodes; lane owns channels (2l, 2l+1) as one
// half2. Each gather = 128B/warp coalesced. Indices broadcast via shfl.
// Output transposed through smem for coalesced fp32 stores.
// ---------------------------------------------------------------------------
__global__ __launch_bounds__(256) void kB(
    const int* __restrict__ ei, float* __restrict__ out)
{
    __shared__ float sm[64 * 33];

    const int tid  = threadIdx.x;
    const int w    = tid >> 5;
    const int lane = tid & 31;
    const int b    = blockIdx.y;
    const int n0   = blockIdx.x * 32;

    const int* e0 = ei + (size_t)b * NN * NK;                 // edge_index[0][b]
    const int* e1 = e0 + (size_t)NB * NN * NK;                // edge_index[1][b]
    const char* yb = (const char*)g_y + ((size_t)b * NN * 256);

    const __half2 NEGI  = __half2half2(__ushort_as_half(0xFC00)); // -inf
    const __half2 SLOPE = __float2half2_rn(0.2f);

    for (int j = 0; j < 4; j++) {
        const int nl = w * 4 + j;
        const int n  = n0 + nl;
        const int base = n * NK;

        // lanes 0-15: e0[k], lanes 16-31: e1[k]
        int v;
        if (lane < 16) v = __ldg(e0 + base + lane);
        else           v = __ldg(e1 + base + (lane - 16));

        __half2 m = NEGI;
#pragma unroll
        for (int k = 0; k < 16; k++) {
            int i0 = __shfl_sync(0xffffffffu, v, k);
            int i1 = __shfl_sync(0xffffffffu, v, k + 16);
            __half2 a = *(const __half2*)(yb + (i1 << 8) + (lane << 2));        // y1
            __half2 c = *(const __half2*)(yb + (i0 << 8) + 128 + (lane << 2));  // y2
            __half2 h = __hadd2(a, c);
            h = __hmax2(h, __hmul2(h, SLOPE));    // LeakyReLU(0.2)
            m = __hmax2(m, h);
        }
        float2 f = __half22float2(m);
        sm[(2 * lane)     * 33 + nl] = f.x;
        sm[(2 * lane + 1) * 33 + nl] = f.y;
    }
    __syncthreads();

#pragma unroll
    for (int i = 0; i < 8; i++) {
        int o = i * 8 + w;
        out[((size_t)(b * NO + o)) * NN + n0 + lane] = sm[o * 33 + lane];
    }
}

extern "C" void kernel_launch(void* const* d_in, const int* in_sizes, int n_in,
                              void* d_out, int out_size)
{
    const float* x     = (const float*)d_in[0];
    const int*   ei    = (const int*)d_in[1];
    const float* W     = (const float*)d_in[2];
    const float* gamma = (const float*)d_in[3];
    const float* beta  = (const float*)d_in[4];
    const float* rmean = (const float*)d_in[5];
    const float* rvar  = (const float*)d_in[6];
    float*       out   = (float*)d_out;

    kA<<<dim3(NN / 128, NB), 256>>>(x, W, gamma, beta, rmean, rvar);
    kB<<<dim3(NN / 32, NB), 256>>>(ei, out);
}

// round 6
// speedup vs baseline: 1.4673x; 1.2619x over previous
#include <cuda_runtime.h>
#include <cuda_fp16.h>

#define NB 4
#define NC 64
#define NN 8192
#define NK 16
#define NO 64
#define EPSV 1e-5f

// Combined y, fp16: [b][n][128] halves. ch 0-63  = y1 = inv*(W1-W2)@x  (gather via e1)
//                                      ch 64-127 = y2 = inv*W2@x + shift (gather via e0)
// One node row = 256B; each gather reads half a row (128B across a warp).
__device__ __align__(16) __half g_y[(size_t)NB * NN * 128];

typedef unsigned long long u64;

__device__ __forceinline__ u64 pk2(float a, float b) {
    u64 r; asm("mov.b64 %0, {%1, %2};" : "=l"(r) : "f"(a), "f"(b)); return r;
}
__device__ __forceinline__ void upk2(u64 v, float& a, float& b) {
    asm("mov.b64 {%0, %1}, %2;" : "=f"(a), "=f"(b) : "l"(v));
}
__device__ __forceinline__ void fma2(u64& d, u64 a, u64 b) {
    asm("fma.rn.f32x2 %0, %1, %2, %0;" : "+l"(d) : "l"(a), "l"(b));
}

#define SW_STRIDE 132   // 128 + 4 pad: 16B-aligned rows, 4-way (not 32-way) STS conflicts

// ---------------------------------------------------------------------------
// Kernel A: y[128 outs][nodes] = M[128x64] @ x[64][nodes], BN folded.
// Block = 128 outs x 64 nodes, 256 threads, thread = 8 outs x 4 nodes
// (16 f32x2 accumulators = 32 regs; ~70 regs total, no spills).
// W staged in two 32-channel chunks (16.9KB) + X tile (16KB) = 33.5KB smem.
// ---------------------------------------------------------------------------
__global__ __launch_bounds__(256, 2) void kA(
    const float* __restrict__ x, const float* __restrict__ W,
    const float* __restrict__ gamma, const float* __restrict__ beta,
    const float* __restrict__ rmean, const float* __restrict__ rvar)
{
    __shared__ float sW[32 * SW_STRIDE];   // [c-in-chunk][out(+pad)], BN inv folded
    __shared__ float sX[64 * 64];          // [c][node]
    __shared__ float sinv[64];

    const int tid = threadIdx.x;
    const int b   = blockIdx.y;
    const int n0  = blockIdx.x * 64;
    const int og  = tid >> 4;              // 16 groups: outs [og*8, og*8+8)
    const int ng  = tid & 15;              // 16 groups: nodes [ng*4, ng*4+4)

    if (tid < 64) sinv[tid] = gamma[tid] * rsqrtf(rvar[tid] + EPSV);

    // Stage X tile: 64 c x 64 nodes, float4-coalesced.
    {
        const float4* xp = (const float4*)(x + (size_t)b * NC * NN + n0);
        for (int i = tid; i < 64 * 16; i += 256) {
            int c = i >> 4, j = i & 15;
            ((float4*)sX)[c * 16 + j] = xp[(size_t)c * (NN / 4) + j];
        }
    }

    // Init accumulators with BN shift (y2 half only, outs 64..127).
    u64 acc[4][4];
    {
        u64 sh[4];
#pragma unroll
        for (int j = 0; j < 4; j++) sh[j] = 0ULL;
        if (og >= 8) {
#pragma unroll
            for (int j = 0; j < 4; j++) {
                int o0 = og * 8 + 2 * j - 64, o1 = o0 + 1;
                float i0 = gamma[o0] * rsqrtf(rvar[o0] + EPSV);
                float i1 = gamma[o1] * rsqrtf(rvar[o1] + EPSV);
                sh[j] = pk2(beta[o0] - rmean[o0] * i0, beta[o1] - rmean[o1] * i1);
            }
        }
#pragma unroll
        for (int j = 0; j < 4; j++)
#pragma unroll
            for (int i = 0; i < 4; i++) acc[j][i] = sh[j];
    }

    for (int cc = 0; cc < 2; cc++) {
        __syncthreads();
        // Stage W chunk: channels [cc*32, cc*32+32). Consecutive threads read
        // consecutive c of one o (coalesced). sW[c][o], o<64 -> (W1-W2)*inv,
        // o>=64 -> W2*inv.
        for (int i = tid; i < 32 * 128; i += 256) {
            int o = i >> 5, cl = i & 31;
            int c = cc * 32 + cl;
            float v;
            if (o < 64) v = (W[o * 128 + c] - W[o * 128 + 64 + c]) * sinv[o];
            else        v = W[(o - 64) * 128 + 64 + c] * sinv[o - 64];
            sW[cl * SW_STRIDE + o] = v;
        }
        __syncthreads();

#pragma unroll 4
        for (int cl = 0; cl < 32; cl++) {
            const float4* wrow = (const float4*)(sW + cl * SW_STRIDE + og * 8);
            float4 w0 = wrow[0], w1 = wrow[1];
            u64 wp[4] = { pk2(w0.x, w0.y), pk2(w0.z, w0.w),
                          pk2(w1.x, w1.y), pk2(w1.z, w1.w) };
            float4 xv = *(const float4*)(sX + (cc * 32 + cl) * 64 + ng * 4);
            u64 xs[4] = { pk2(xv.x, xv.x), pk2(xv.y, xv.y),
                          pk2(xv.z, xv.z), pk2(xv.w, xv.w) };
#pragma unroll
            for (int i = 0; i < 4; i++)
#pragma unroll
                for (int j = 0; j < 4; j++) fma2(acc[j][i], wp[j], xs[i]);
        }
    }

    // Epilogue: 4 nodes x one 16B fp16 store each.
#pragma unroll
    for (int i = 0; i < 4; i++) {
        int n = n0 + ng * 4 + i;
        __half2 h[4];
#pragma unroll
        for (int j = 0; j < 4; j++) {
            float a, bq; upk2(acc[j][i], a, bq);
            h[j] = __floats2half2_rn(a, bq);
        }
        *(uint4*)(&g_y[(((size_t)b * NN + n) << 7) + og * 8]) = *(uint4*)h;
    }
}

// ---------------------------------------------------------------------------
// Kernel B: edge gather + leaky + max, fp16 y.
// Block = 32 nodes, 256 threads. Indices pre-staged to smem (1 coalesced
// int4 pass), k-loop reads them via broadcast LDS -> 32 independent LDG.32
// per node, high MLP. Lane owns channel pair (one half2).
// Output transposed through smem for coalesced fp32 stores.
// ---------------------------------------------------------------------------
__global__ __launch_bounds__(256) void kB(
    const int* __restrict__ ei, float* __restrict__ out)
{
    __shared__ int  sIdx[1024];      // [0:512) e0 rows, [512:1024) e1 rows
    __shared__ float sm[64 * 33];

    const int tid  = threadIdx.x;
    const int w    = tid >> 5;
    const int lane = tid & 31;
    const int b    = blockIdx.y;
    const int n0   = blockIdx.x * 32;

    const int* e0 = ei + (size_t)b * NN * NK + (size_t)n0 * NK;   // 512 ints contiguous
    const int* e1 = e0 + (size_t)NB * NN * NK;

    // Stage indices: 256 int4 loads total, 1 per thread.
    if (tid < 128) ((int4*)sIdx)[tid] = ((const int4*)e0)[tid];
    else           ((int4*)sIdx)[tid] = ((const int4*)e1)[tid - 128];
    __syncthreads();

    const char* yb = (const char*)g_y + ((size_t)b * NN * 256);
    const __half2 NEGI  = __half2half2(__ushort_as_half(0xFC00)); // -inf
    const __half2 SLOPE = __float2half2_rn(0.2f);

#pragma unroll
    for (int j = 0; j < 4; j++) {
        const int nl = w * 4 + j;
        const int* i0p = &sIdx[nl * NK];
        const int* i1p = &sIdx[512 + nl * NK];

        __half2 m = NEGI;
#pragma unroll
        for (int k = 0; k < 16; k++) {
            int i0 = i0p[k];                 // broadcast LDS
            int i1 = i1p[k];
            __half2 a = *(const __half2*)(yb + (i1 << 8) + (lane << 2));        // y1
            __half2 c = *(const __half2*)(yb + (i0 << 8) + 128 + (lane << 2));  // y2
            __half2 h = __hadd2(a, c);
            h = __hmax2(h, __hmul2(h, SLOPE));    // LeakyReLU(0.2)
            m = __hmax2(m, h);
        }
        float2 f = __half22float2(m);
        sm[(2 * lane)     * 33 + nl] = f.x;
        sm[(2 * lane + 1) * 33 + nl] = f.y;
    }
    __syncthreads();

#pragma unroll
    for (int i = 0; i < 8; i++) {
        int o = i * 8 + w;
        out[((size_t)(b * NO + o)) * NN + n0 + lane] = sm[o * 33 + lane];
    }
}

extern "C" void kernel_launch(void* const* d_in, const int* in_sizes, int n_in,
                              void* d_out, int out_size)
{
    const float* x     = (const float*)d_in[0];
    const int*   ei    = (const int*)d_in[1];
    const float* W     = (const float*)d_in[2];
    const float* gamma = (const float*)d_in[3];
    const float* beta  = (const float*)d_in[4];
    const float* rmean = (const float*)d_in[5];
    const float* rvar  = (const float*)d_in[6];
    float*       out   = (float*)d_out;

    kA<<<dim3(NN / 64, NB), 256>>>(x, W, gamma, beta, rmean, rvar);
    kB<<<dim3(NN / 32, NB), 256>>>(ei, out);
}

// round 9
// speedup vs baseline: 1.6270x; 1.1089x over previous
// R8 resubmission of the R7 kernel (two consecutive broker-side container
// failures; kernel never executed).
#include <cuda_runtime.h>
#include <cuda_fp16.h>

#define NB 4
#define NC 64
#define NN 8192
#define NK 16
#define NO 64
#define EPSV 1e-5f

// Combined y, fp16: [b][n][128] halves. ch 0-63  = y1 = inv*(W1-W2)@x  (gather via e1)
//                                      ch 64-127 = y2 = inv*W2@x + shift (gather via e0)
// One node row = 256B; each gather reads half a row (128B).
__device__ __align__(16) __half g_y[(size_t)NB * NN * 128];

typedef unsigned long long u64;

__device__ __forceinline__ u64 pk2(float a, float b) {
    u64 r; asm("mov.b64 %0, {%1, %2};" : "=l"(r) : "f"(a), "f"(b)); return r;
}
__device__ __forceinline__ void upk2(u64 v, float& a, float& b) {
    asm("mov.b64 {%0, %1}, %2;" : "=f"(a), "=f"(b) : "l"(v));
}
__device__ __forceinline__ void fma2(u64& d, u64 a, u64 b) {
    asm("fma.rn.f32x2 %0, %1, %2, %0;" : "+l"(d) : "l"(a), "l"(b));
}

#define SW_STRIDE 132   // 128 + 4 pad: 16B-aligned rows

// ---------------------------------------------------------------------------
// Kernel A: y[128 outs][nodes] = M[128x64] @ x[64][nodes], BN folded.
// Block = 128 outs x 128 nodes, 256 threads, thread = 8 outs x 8 nodes.
// Both W and X staged in 32-channel chunks: 16.9KB + 16KB smem.
// Per iter/thread: 4 LDS.128 vs 32 FMA2 -> smem and FMA2 pipes balanced.
// ---------------------------------------------------------------------------
__global__ __launch_bounds__(256, 2) void kA(
    const float* __restrict__ x, const float* __restrict__ W,
    const float* __restrict__ gamma, const float* __restrict__ beta,
    const float* __restrict__ rmean, const float* __restrict__ rvar)
{
    __shared__ float sW[32 * SW_STRIDE];   // [c-in-chunk][out(+pad)], BN inv folded
    __shared__ float sX[32 * 128];         // [c-in-chunk][node]
    __shared__ float sinv[64];

    const int tid = threadIdx.x;
    const int b   = blockIdx.y;
    const int n0  = blockIdx.x * 128;
    const int og  = tid >> 4;              // outs [og*8, og*8+8)
    const int ng  = tid & 15;              // nodes [ng*8, ng*8+8)

    if (tid < 64) sinv[tid] = gamma[tid] * rsqrtf(rvar[tid] + EPSV);

    // Init accumulators with BN shift (y2 half only, outs 64..127).
    u64 acc[4][8];
    {
        u64 sh[4];
#pragma unroll
        for (int j = 0; j < 4; j++) sh[j] = 0ULL;
        if (og >= 8) {
#pragma unroll
            for (int j = 0; j < 4; j++) {
                int o0 = og * 8 + 2 * j - 64, o1 = o0 + 1;
                float i0 = gamma[o0] * rsqrtf(rvar[o0] + EPSV);
                float i1 = gamma[o1] * rsqrtf(rvar[o1] + EPSV);
                sh[j] = pk2(beta[o0] - rmean[o0] * i0, beta[o1] - rmean[o1] * i1);
            }
        }
#pragma unroll
        for (int j = 0; j < 4; j++)
#pragma unroll
            for (int i = 0; i < 8; i++) acc[j][i] = sh[j];
    }

    for (int cc = 0; cc < 2; cc++) {
        __syncthreads();
        // Stage X chunk: 32 c x 128 nodes, float4-coalesced.
        {
            const float4* xp = (const float4*)(x + (size_t)b * NC * NN
                                               + (size_t)(cc * 32) * NN + n0);
            for (int i = tid; i < 32 * 32; i += 256) {
                int c = i >> 5, j = i & 31;
                ((float4*)sX)[c * 32 + j] = xp[(size_t)c * (NN / 4) + j];
            }
        }
        // Stage W chunk: consecutive threads read consecutive c of one o
        // (coalesced). sW[c][o]: o<64 -> (W1-W2)*inv, o>=64 -> W2*inv.
        for (int i = tid; i < 32 * 128; i += 256) {
            int o = i >> 5, cl = i & 31;
            int c = cc * 32 + cl;
            float v;
            if (o < 64) v = (W[o * 128 + c] - W[o * 128 + 64 + c]) * sinv[o];
            else        v = W[(o - 64) * 128 + 64 + c] * sinv[o - 64];
            sW[cl * SW_STRIDE + o] = v;
        }
        __syncthreads();

#pragma unroll 4
        for (int cl = 0; cl < 32; cl++) {
            const float4* wrow = (const float4*)(sW + cl * SW_STRIDE + og * 8);
            float4 w0 = wrow[0], w1 = wrow[1];
            u64 wp[4] = { pk2(w0.x, w0.y), pk2(w0.z, w0.w),
                          pk2(w1.x, w1.y), pk2(w1.z, w1.w) };
            const float4* xrow = (const float4*)(sX + cl * 128 + ng * 8);
            float4 x0 = xrow[0], x1 = xrow[1];
            u64 xs[8] = { pk2(x0.x, x0.x), pk2(x0.y, x0.y),
                          pk2(x0.z, x0.z), pk2(x0.w, x0.w),
                          pk2(x1.x, x1.x), pk2(x1.y, x1.y),
                          pk2(x1.z, x1.z), pk2(x1.w, x1.w) };
#pragma unroll
            for (int i = 0; i < 8; i++)
#pragma unroll
                for (int j = 0; j < 4; j++) fma2(acc[j][i], wp[j], xs[i]);
        }
    }

    // Epilogue: 8 nodes x one 16B fp16 store each.
#pragma unroll
    for (int i = 0; i < 8; i++) {
        int n = n0 + ng * 8 + i;
        __half2 h[4];
#pragma unroll
        for (int j = 0; j < 4; j++) {
            float a, bq; upk2(acc[j][i], a, bq);
            h[j] = __floats2half2_rn(a, bq);
        }
        *(uint4*)(&g_y[(((size_t)b * NN + n) << 7) + og * 8]) = *(uint4*)h;
    }
}

// ---------------------------------------------------------------------------
// Kernel B: edge gather + leaky + max, fp16 y, wide gathers.
// Block = 32 nodes, 256 threads. Warp handles 4 nodes at once: 8 lanes per
// node, each lane owns 8 channels (uint4 = 4 half2). Per k: ONE LDG.128
// covers y1 for all 4 nodes, one more for y2 -> 2.4x fewer instructions
// per gathered byte than the narrow version; L2-byte floor becomes binding.
// ---------------------------------------------------------------------------
__global__ __launch_bounds__(256) void kB(
    const int* __restrict__ ei, float* __restrict__ out)
{
    __shared__ int  sIdx[1024];      // [0:512) e0 rows, [512:1024) e1 rows
    __shared__ float sm[64 * 33];

    const int tid  = threadIdx.x;
    const int w    = tid >> 5;
    const int lane = tid & 31;
    const int b    = blockIdx.y;
    const int n0   = blockIdx.x * 32;

    const int* e0 = ei + (size_t)b * NN * NK + (size_t)n0 * NK;   // 512 ints contiguous
    const int* e1 = e0 + (size_t)NB * NN * NK;

    // Stage indices: 256 int4 loads total, 1 per thread.
    if (tid < 128) ((int4*)sIdx)[tid] = ((const int4*)e0)[tid];
    else           ((int4*)sIdx)[tid] = ((const int4*)e1)[tid - 128];
    __syncthreads();

    const char* yb = (const char*)g_y + ((size_t)b * NN * 256);
    const __half2 NEGI  = __half2half2(__ushort_as_half(0xFC00)); // -inf
    const __half2 SLOPE = __float2half2_rn(0.2f);

    const int nl  = w * 4 + (lane >> 3);   // node within block (0..31)
    const int sub = lane & 7;              // 8-ch slice within node
    const int* i0p = &sIdx[nl * NK];
    const int* i1p = &sIdx[512 + nl * NK];

    __half2 m[4] = {NEGI, NEGI, NEGI, NEGI};
#pragma unroll
    for (int k = 0; k < 16; k++) {
        int i0 = i0p[k];
        int i1 = i1p[k];
        uint4 av = *(const uint4*)(yb + (i1 << 8) + (sub << 4));        // y1 slice
        uint4 cv = *(const uint4*)(yb + (i0 << 8) + 128 + (sub << 4));  // y2 slice
        const __half2* a = (const __half2*)&av;
        const __half2* c = (const __half2*)&cv;
#pragma unroll
        for (int q = 0; q < 4; q++) {
            __half2 h = __hadd2(a[q], c[q]);
            h = __hmax2(h, __hmul2(h, SLOPE));    // LeakyReLU(0.2)
            m[q] = __hmax2(m[q], h);
        }
    }
    // Lane holds max for node nl, channels [sub*8, sub*8+8).
#pragma unroll
    for (int q = 0; q < 4; q++) {
        float2 f = __half22float2(m[q]);
        sm[(sub * 8 + 2 * q)     * 33 + nl] = f.x;
        sm[(sub * 8 + 2 * q + 1) * 33 + nl] = f.y;
    }
    __syncthreads();

#pragma unroll
    for (int i = 0; i < 8; i++) {
        int o = i * 8 + w;
        out[((size_t)(b * NO + o)) * NN + n0 + lane] = sm[o * 33 + lane];
    }
}

extern "C" void kernel_launch(void* const* d_in, const int* in_sizes, int n_in,
                              void* d_out, int out_size)
{
    const float* x     = (const float*)d_in[0];
    const int*   ei    = (const int*)d_in[1];
    const float* W     = (const float*)d_in[2];
    const float* gamma = (const float*)d_in[3];
    const float* beta  = (const float*)d_in[4];
    const float* rmean = (const float*)d_in[5];
    const float* rvar  = (const float*)d_in[6];
    float*       out   = (float*)d_out;

    kA<<<dim3(NN / 128, NB), 256>>>(x, W, gamma, beta, rmean, rvar);
    kB<<<dim3(NN / 32, NB), 256>>>(ei, out);
}

// round 10
// speedup vs baseline: 2.3046x; 1.4165x over previous
#include <cuda_runtime.h>
#include <cuda_fp16.h>
#include <mma.h>
using namespace nvcuda;

#define NB 4
#define NC 64
#define NN 8192
#define NK 16
#define NO 64
#define EPSV 1e-5f

// Combined y, fp16: [b][n][128] halves. ch 0-63  = y1 = inv*(W1-W2)@x  (gather via e1)
//                                      ch 64-127 = y2 = inv*W2@x + shift (gather via e0)
__device__ __align__(16) __half g_y[(size_t)NB * NN * 128];

#define XH_LD 136   // sXh [c][n] fp16 rows (pad 8; multiple of 8 for wmma ldm)
#define WH_LD 136   // sWh [c][o] fp16 rows
#define ST_LD 40    // epilogue staging row stride in floats (mult of 8, not mult of 32)

#define SMEM_XH    0                      // 64*136*2 = 17408
#define SMEM_WH    17408                  // 64*136*2 = 17408
#define SMEM_SHIFT 34816                  // 128 floats = 512
#define SMEM_TOT   (34816 + 512)
// Epilogue staging reuses bytes [0, 20480) (8 warps x 16 x 40 floats).

// ---------------------------------------------------------------------------
// Kernel A (tensor cores): y[n][o] for a 128-node x 128-out block.
// 8 warps; warp = 16 nodes x 128 outs (8 wmma col tiles), 4 k-steps of 16 c.
// A = X tile, col_major straight from gmem layout [c][n] (no transpose).
// B = folded W [c][o] fp16. BN shift added in epilogue before fp16 convert.
// ---------------------------------------------------------------------------
__global__ __launch_bounds__(256, 2) void kA(
    const float* __restrict__ x, const float* __restrict__ W,
    const float* __restrict__ gamma, const float* __restrict__ beta,
    const float* __restrict__ rmean, const float* __restrict__ rvar)
{
    __shared__ __align__(16) char smem[SMEM_TOT];
    __half* sXh    = (__half*)(smem + SMEM_XH);
    __half* sWh    = (__half*)(smem + SMEM_WH);
    float*  sshift = (float*)(smem + SMEM_SHIFT);
    __shared__ float sinv[64];

    const int tid = threadIdx.x;
    const int b   = blockIdx.y;
    const int n0b = blockIdx.x * 128;
    const int w   = tid >> 5;
    const int lane = tid & 31;

    // BN constants.
    if (tid < 64) sinv[tid] = gamma[tid] * rsqrtf(rvar[tid] + EPSV);
    if (tid < 128) {
        float s = 0.f;
        if (tid >= 64) {
            int o2 = tid - 64;
            s = beta[o2] - rmean[o2] * gamma[o2] * rsqrtf(rvar[o2] + EPSV);
        }
        sshift[tid] = s;
    }

    // Stage X tile: [64 c][128 n] fp32 -> fp16, coalesced float4 reads.
    {
        const float4* xp = (const float4*)(x + (size_t)b * NC * NN + n0b);
        for (int i = tid; i < 64 * 32; i += 256) {
            int c = i >> 5, j = i & 31;
            float4 v = xp[(size_t)c * (NN / 4) + j];
            __half2 h0 = __floats2half2_rn(v.x, v.y);
            __half2 h1 = __floats2half2_rn(v.z, v.w);
            __half2* dst = (__half2*)&sXh[c * XH_LD + 4 * j];
            dst[0] = h0; dst[1] = h1;
        }
    }
    __syncthreads();   // sinv ready for W fold

    // Stage folded W: sWh[c][o]; o<64 -> (W1-W2)*inv, o>=64 -> W2*inv.
    // Thread handles an o-quad at one c; lanes have consecutive c (coalesced LDG).
    for (int i = tid; i < 2048; i += 256) {
        int q = i >> 6, c = i & 63;
        int o0 = q * 4;
        float v[4];
        if (o0 < 64) {
#pragma unroll
            for (int j = 0; j < 4; j++) {
                int o = o0 + j;
                v[j] = (W[o * 128 + c] - W[o * 128 + 64 + c]) * sinv[o];
            }
        } else {
#pragma unroll
            for (int j = 0; j < 4; j++) {
                int o2 = o0 + j - 64;
                v[j] = W[o2 * 128 + 64 + c] * sinv[o2];
            }
        }
        __half2* dst = (__half2*)&sWh[c * WH_LD + o0];
        dst[0] = __floats2half2_rn(v[0], v[1]);
        dst[1] = __floats2half2_rn(v[2], v[3]);
    }
    __syncthreads();

    // Mainloop: warp covers nodes [w*16, w*16+16), all 128 outs.
    const int n0 = w * 16;
    wmma::fragment<wmma::matrix_a, 16, 16, 16, __half, wmma::col_major> af;
    wmma::fragment<wmma::matrix_b, 16, 16, 16, __half, wmma::row_major> bf;
    wmma::fragment<wmma::accumulator, 16, 16, 16, float> acc[8];
#pragma unroll
    for (int t = 0; t < 8; t++) wmma::fill_fragment(acc[t], 0.0f);

#pragma unroll
    for (int k = 0; k < 4; k++) {
        wmma::load_matrix_sync(af, sXh + k * 16 * XH_LD + n0, XH_LD);
#pragma unroll
        for (int t = 0; t < 8; t++) {
            wmma::load_matrix_sync(bf, sWh + k * 16 * WH_LD + t * 16, WH_LD);
            wmma::mma_sync(acc[t], af, bf, acc[t]);
        }
    }
    __syncthreads();   // smem about to be reused for staging

    // Epilogue: 4 passes of 32 outs via per-warp smem staging.
    float* st = (float*)smem + w * 16 * ST_LD;
    const int r = lane & 15, h = lane >> 4;   // row (node), 16-out half
#pragma unroll
    for (int p = 0; p < 4; p++) {
        wmma::store_matrix_sync(st,      acc[2 * p],     ST_LD, wmma::mem_row_major);
        wmma::store_matrix_sync(st + 16, acc[2 * p + 1], ST_LD, wmma::mem_row_major);
        __syncwarp();
        int ob = p * 32 + h * 16;
        const float* row = st + r * ST_LD + h * 16;
        __half2 hh[8];
#pragma unroll
        for (int j = 0; j < 4; j++) {
            float4 f = *(const float4*)(row + 4 * j);
            float4 s = *(const float4*)(sshift + ob + 4 * j);
            hh[2 * j]     = __floats2half2_rn(f.x + s.x, f.y + s.y);
            hh[2 * j + 1] = __floats2half2_rn(f.z + s.z, f.w + s.w);
        }
        int n = n0b + n0 + r;
        *(uint4*)(&g_y[(((size_t)b * NN + n) << 7) + ob])     = *(uint4*)&hh[0];
        *(uint4*)(&g_y[(((size_t)b * NN + n) << 7) + ob + 8]) = *(uint4*)&hh[4];
        __syncwarp();
    }
}

// ---------------------------------------------------------------------------
// Kernel B: edge gather + leaky + max, fp16 y, wide gathers (unchanged R9).
// ---------------------------------------------------------------------------
__global__ __launch_bounds__(256) void kB(
    const int* __restrict__ ei, float* __restrict__ out)
{
    __shared__ int  sIdx[1024];      // [0:512) e0 rows, [512:1024) e1 rows
    __shared__ float sm[64 * 33];

    const int tid  = threadIdx.x;
    const int w    = tid >> 5;
    const int lane = tid & 31;
    const int b    = blockIdx.y;
    const int n0   = blockIdx.x * 32;

    const int* e0 = ei + (size_t)b * NN * NK + (size_t)n0 * NK;
    const int* e1 = e0 + (size_t)NB * NN * NK;

    if (tid < 128) ((int4*)sIdx)[tid] = ((const int4*)e0)[tid];
    else           ((int4*)sIdx)[tid] = ((const int4*)e1)[tid - 128];
    __syncthreads();

    const char* yb = (const char*)g_y + ((size_t)b * NN * 256);
    const __half2 NEGI  = __half2half2(__ushort_as_half(0xFC00));
    const __half2 SLOPE = __float2half2_rn(0.2f);

    const int nl  = w * 4 + (lane >> 3);
    const int sub = lane & 7;
    const int* i0p = &sIdx[nl * NK];
    const int* i1p = &sIdx[512 + nl * NK];

    __half2 m[4] = {NEGI, NEGI, NEGI, NEGI};
#pragma unroll
    for (int k = 0; k < 16; k++) {
        int i0 = i0p[k];
        int i1 = i1p[k];
        uint4 av = *(const uint4*)(yb + (i1 << 8) + (sub << 4));        // y1
        uint4 cv = *(const uint4*)(yb + (i0 << 8) + 128 + (sub << 4));  // y2
        const __half2* a = (const __half2*)&av;
        const __half2* c = (const __half2*)&cv;
#pragma unroll
        for (int q = 0; q < 4; q++) {
            __half2 hq = __hadd2(a[q], c[q]);
            hq = __hmax2(hq, __hmul2(hq, SLOPE));
            m[q] = __hmax2(m[q], hq);
        }
    }
#pragma unroll
    for (int q = 0; q < 4; q++) {
        float2 f = __half22float2(m[q]);
        sm[(sub * 8 + 2 * q)     * 33 + nl] = f.x;
        sm[(sub * 8 + 2 * q + 1) * 33 + nl] = f.y;
    }
    __syncthreads();

#pragma unroll
    for (int i = 0; i < 8; i++) {
        int o = i * 8 + w;
        out[((size_t)(b * NO + o)) * NN + n0 + lane] = sm[o * 33 + lane];
    }
}

extern "C" void kernel_launch(void* const* d_in, const int* in_sizes, int n_in,
                              void* d_out, int out_size)
{
    const float* x     = (const float*)d_in[0];
    const int*   ei    = (const int*)d_in[1];
    const float* W     = (const float*)d_in[2];
    const float* gamma = (const float*)d_in[3];
    const float* beta  = (const float*)d_in[4];
    const float* rmean = (const float*)d_in[5];
    const float* rvar  = (const float*)d_in[6];
    float*       out   = (float*)d_out;

    kA<<<dim3(NN / 128, NB), 256>>>(x, W, gamma, beta, rmean, rvar);
    kB<<<dim3(NN / 32, NB), 256>>>(ei, out);
}